// round 2
// baseline (speedup 1.0000x reference)
#include <cuda_runtime.h>
#include <cuda_fp16.h>
#include <cstdint>

// ---------------- problem constants ----------------
#define HDIM   4096
#define MTOT   16384
#define NGRP   8
#define I2     3072
#define IHALF  1536
#define MSPLIT 2048

// ---------------- GEMM tiling ----------------
#define BM      128
#define BN      128            // output tile cols (gate AND up computed for these cols)
#define KC      64              // fp16 elems per K chunk (128 bytes per row)
#define NSTAGE  4
#define NITER   (HDIM / KC)     // 64

#define A_BYTES     (BM * KC * 2)              // 16384
#define B_BYTES     (BN * KC * 2)              // 16384
#define STAGE_BYTES (A_BYTES + 2 * B_BYTES)    // 49152
#define SMEM_BYTES  (NSTAGE * STAGE_BYTES)     // 196608

// ---------------- fp16 scratch (device globals; no allocation) ----------------
__device__ __align__(1024) __half g_xh[(size_t)MTOT * HDIM];
__device__ __align__(1024) __half g_wh[(size_t)NGRP * I2 * HDIM];

// ---------------- helpers ----------------
__device__ __forceinline__ uint32_t smem_u32(const void* p) {
    uint32_t a;
    asm("{ .reg .u64 t; cvta.to.shared.u64 t, %1; cvt.u32.u64 %0, t; }" : "=r"(a) : "l"(p));
    return a;
}
__device__ __forceinline__ uint32_t swz(uint32_t o) {
    // 128B-row swizzle: XOR 16B-column bits [6:4] with row bits [9:7]
    return o ^ ((o >> 3) & 0x70);
}
__device__ __forceinline__ void cp16(uint32_t s, const void* g) {
    asm volatile("cp.async.cg.shared.global [%0], [%1], 16;" :: "r"(s), "l"(g));
}
__device__ __forceinline__ void cp_commit() {
    asm volatile("cp.async.commit_group;" ::: "memory");
}
template <int N>
__device__ __forceinline__ void cp_wait() {
    asm volatile("cp.async.wait_group %0;" :: "n"(N) : "memory");
}
__device__ __forceinline__ void ldmx4(uint32_t& r0, uint32_t& r1, uint32_t& r2, uint32_t& r3,
                                      uint32_t addr) {
    asm volatile("ldmatrix.sync.aligned.m8n8.x4.shared.b16 {%0,%1,%2,%3}, [%4];"
                 : "=r"(r0), "=r"(r1), "=r"(r2), "=r"(r3) : "r"(addr));
}
__device__ __forceinline__ void mma16816(float* c, const uint32_t* a, const uint32_t* b) {
    asm volatile(
        "mma.sync.aligned.m16n8k16.row.col.f32.f16.f16.f32 "
        "{%0,%1,%2,%3}, {%4,%5,%6,%7}, {%8,%9}, {%0,%1,%2,%3};"
        : "+f"(c[0]), "+f"(c[1]), "+f"(c[2]), "+f"(c[3])
        : "r"(a[0]), "r"(a[1]), "r"(a[2]), "r"(a[3]), "r"(b[0]), "r"(b[1]));
}

// ---------------- fp32 -> fp16 convert ----------------
__global__ void cvt_f32_f16(const float4* __restrict__ in, uint2* __restrict__ out, int n4) {
    int i = blockIdx.x * blockDim.x + threadIdx.x;
    if (i >= n4) return;
    float4 v = in[i];
    __half2 h0 = __floats2half2_rn(v.x, v.y);
    __half2 h1 = __floats2half2_rn(v.z, v.w);
    uint2 u;
    u.x = *reinterpret_cast<uint32_t*>(&h0);
    u.y = *reinterpret_cast<uint32_t*>(&h1);
    out[i] = u;
}

// ---------------- fused GEMM + SwiGLU ----------------
// CTA tile: 128 rows x 128 output cols. Computes gate = x@wg^T and up = x@wu^T
// simultaneously; epilogue: out = silu(gate) * up.
// 8 warps: wm = wid/4 in {0,1} (64 rows each), wn = wid%4 (32 cols each).
__global__ void __launch_bounds__(256, 1)
teswiglu_gemm(const __half* __restrict__ xh, const __half* __restrict__ wh,
              float* __restrict__ out) {
    extern __shared__ __align__(128) char smem[];
    uint32_t sbase = smem_u32(smem);
    int tid = threadIdx.x;
    int wid = tid >> 5;
    int lid = tid & 31;

    int bid = blockIdx.x;
    int nt = bid % (IHALF / BN);                 // 12
    int mt = (bid / (IHALF / BN)) % (MSPLIT / BM); // 16
    int g  = bid / ((IHALF / BN) * (MSPLIT / BM));

    const int m0 = g * MSPLIT + mt * BM;
    const size_t a_row0 = (size_t)m0 * HDIM;
    const size_t bg_row0 = ((size_t)g * I2 + nt * BN) * HDIM;
    const size_t bu_row0 = bg_row0 + (size_t)IHALF * HDIM;

    const __half* Ag = xh + a_row0;
    const __half* Bg = wh + bg_row0;
    const __half* Bu = wh + bu_row0;

    // ---- pipeline load of one stage ----
    auto load_stage = [&](int s, int k0) {
        uint32_t st = sbase + s * STAGE_BYTES;
        #pragma unroll
        for (int c = 0; c < 4; c++) {
            int idx = tid + c * 256;
            int row = idx >> 3, seg = idx & 7;
            cp16(st + swz(row * 128 + seg * 16), Ag + (size_t)row * HDIM + k0 + seg * 8);
        }
        #pragma unroll
        for (int c = 0; c < 4; c++) {
            int idx = tid + c * 256;
            int row = idx >> 3, seg = idx & 7;
            uint32_t so = swz(row * 128 + seg * 16);
            const size_t go = (size_t)row * HDIM + k0 + seg * 8;
            cp16(st + A_BYTES + so, Bg + go);
            cp16(st + A_BYTES + B_BYTES + so, Bu + go);
        }
        cp_commit();
    };

    // prologue: fill NSTAGE-1 stages
    #pragma unroll
    for (int s = 0; s < NSTAGE - 1; s++) load_stage(s, s * KC);

    const int wm = wid >> 2;      // 0..1
    const int wn = wid & 3;       // 0..3

    float cg[4][4][4];            // [mi][n8 frag][4]
    float cu[4][4][4];
    #pragma unroll
    for (int a = 0; a < 4; a++)
        #pragma unroll
        for (int b = 0; b < 4; b++)
            #pragma unroll
            for (int q = 0; q < 4; q++) { cg[a][b][q] = 0.f; cu[a][b][q] = 0.f; }

    // lane address components (constant per thread)
    const int la_row = (lid & 7) + ((lid >> 3) & 1) * 8;   // A: +8 rows for matrices 1,3
    const int la_kb  = ((lid >> 4) & 1) * 16;              // A: +16B for matrices 2,3
    const int lb_row = (lid & 7) + ((lid >> 4) & 1) * 8;   // B: +8 n-rows for matrices 2,3
    const int lb_kb  = ((lid >> 3) & 1) * 16;              // B: +16B for matrices 1,3

    for (int it = 0; it < NITER; it++) {
        cp_wait<NSTAGE - 2>();
        __syncthreads();
        int jn = it + NSTAGE - 1;
        if (jn < NITER) load_stage(jn % NSTAGE, jn * KC);

        uint32_t st = sbase + (it % NSTAGE) * STAGE_BYTES;
        uint32_t sA = st;
        uint32_t sBg = st + A_BYTES;
        uint32_t sBu = st + A_BYTES + B_BYTES;

        #pragma unroll
        for (int ki = 0; ki < 4; ki++) {
            // A fragments: 4 m16 blocks
            uint32_t a[4][4];
            #pragma unroll
            for (int mi = 0; mi < 4; mi++) {
                int row = wm * 64 + mi * 16 + la_row;
                ldmx4(a[mi][0], a[mi][1], a[mi][2], a[mi][3],
                      sA + swz(row * 128 + ki * 32 + la_kb));
            }
            // B fragments: 4 n8 frags for gate + 4 for up
            uint32_t bg[4][2], bu[4][2];
            #pragma unroll
            for (int nj = 0; nj < 2; nj++) {
                int row = wn * 32 + nj * 16 + lb_row;
                uint32_t off = swz(row * 128 + ki * 32 + lb_kb);
                ldmx4(bg[2 * nj][0], bg[2 * nj][1], bg[2 * nj + 1][0], bg[2 * nj + 1][1],
                      sBg + off);
                ldmx4(bu[2 * nj][0], bu[2 * nj][1], bu[2 * nj + 1][0], bu[2 * nj + 1][1],
                      sBu + off);
            }
            #pragma unroll
            for (int mi = 0; mi < 4; mi++) {
                #pragma unroll
                for (int f = 0; f < 4; f++) {
                    mma16816(cg[mi][f], a[mi], bg[f]);
                    mma16816(cu[mi][f], a[mi], bu[f]);
                }
            }
        }
    }

    // ---- epilogue: silu(gate) * up, write fp32 ----
    #pragma unroll
    for (int mi = 0; mi < 4; mi++) {
        #pragma unroll
        for (int f = 0; f < 4; f++) {
            int row = m0 + wm * 64 + mi * 16 + (lid >> 2);
            int col = nt * BN + wn * 32 + f * 8 + 2 * (lid & 3);
            float o[4];
            #pragma unroll
            for (int q = 0; q < 4; q++) {
                float gv = cg[mi][f][q];
                float uv = cu[mi][f][q];
                o[q] = gv / (1.0f + __expf(-gv)) * uv;
            }
            *reinterpret_cast<float2*>(out + (size_t)row * IHALF + col) =
                make_float2(o[0], o[1]);
            *reinterpret_cast<float2*>(out + (size_t)(row + 8) * IHALF + col) =
                make_float2(o[2], o[3]);
        }
    }
}

// ---------------- host launch ----------------
extern "C" void kernel_launch(void* const* d_in, const int* in_sizes, int n_in,
                              void* d_out, int out_size) {
    const float* x = (const float*)d_in[0];
    const float* w = (const float*)d_in[1];
    float* out = (float*)d_out;

    void* xh_ptr = nullptr;
    void* wh_ptr = nullptr;
    cudaGetSymbolAddress(&xh_ptr, g_xh);
    cudaGetSymbolAddress(&wh_ptr, g_wh);

    {
        int n4x = (MTOT * HDIM) / 4;
        int n4w = (NGRP * I2 * HDIM) / 4;
        cvt_f32_f16<<<n4x / 256, 256>>>((const float4*)x, (uint2*)xh_ptr, n4x);
        cvt_f32_f16<<<n4w / 256, 256>>>((const float4*)w, (uint2*)wh_ptr, n4w);
    }

    cudaFuncSetAttribute(teswiglu_gemm, cudaFuncAttributeMaxDynamicSharedMemorySize, SMEM_BYTES);
    int grid = NGRP * (MSPLIT / BM) * (IHALF / BN);  // 8*16*12 = 1536
    teswiglu_gemm<<<grid, 256, SMEM_BYTES>>>((const __half*)xh_ptr, (const __half*)wh_ptr, out);
}